// round 2
// baseline (speedup 1.0000x reference)
#include <cuda_runtime.h>
#include <math_constants.h>

// Problem constants
#define B_ 4
#define N_ 2048
#define C_ 1024
#define H_ 16
#define D_ 64
#define SCALE_ 0.125f   // 1/sqrt(64)

// Scratch (device globals: allocation-free)
__device__ float g_q[B_ * H_ * N_ * D_];     // [B*H][N][D]
__device__ float g_k[B_ * H_ * N_ * D_];
__device__ float g_v[B_ * H_ * N_ * D_];
__device__ float g_att[B_ * N_ * C_];        // [B][N][C]

// ---------------------------------------------------------------------------
// Kernel 1: QKV GEMM.  X[8192,1024] @ W[1024,3072] + bias -> Q/K/V [B*H][N][D]
// 128x128x16 tiles, 256 threads, 8x8 per-thread micro-tile.
// ---------------------------------------------------------------------------
__global__ __launch_bounds__(256) void qkv_gemm_kernel(
    const float* __restrict__ X, const float* __restrict__ W,
    const float* __restrict__ bias)
{
    const int BK = 16;
    __shared__ float As[16][128];
    __shared__ float Bs[16][128];

    const int tid = threadIdx.x;
    const int m0 = blockIdx.y * 128;
    const int n0 = blockIdx.x * 128;
    const int tx = tid & 15;
    const int ty = tid >> 4;

    float acc[8][8];
#pragma unroll
    for (int i = 0; i < 8; i++)
#pragma unroll
        for (int j = 0; j < 8; j++) acc[i][j] = 0.f;

    for (int k0 = 0; k0 < C_; k0 += BK) {
        // Load A tile (128 x 16): 512 float4 slots, 2 per thread.
#pragma unroll
        for (int i = 0; i < 2; i++) {
            int s = tid * 2 + i;
            int m = s >> 2, kq = s & 3;
            float4 v = *(const float4*)(X + (size_t)(m0 + m) * C_ + k0 + kq * 4);
            As[kq * 4 + 0][m] = v.x;
            As[kq * 4 + 1][m] = v.y;
            As[kq * 4 + 2][m] = v.z;
            As[kq * 4 + 3][m] = v.w;
        }
        // Load B tile (16 x 128): 512 float4 slots, 2 per thread.
#pragma unroll
        for (int i = 0; i < 2; i++) {
            int s = tid * 2 + i;
            int k = s >> 5, n4 = s & 31;
            *(float4*)(&Bs[k][n4 * 4]) =
                *(const float4*)(W + (size_t)(k0 + k) * (3 * C_) + n0 + n4 * 4);
        }
        __syncthreads();

#pragma unroll
        for (int k = 0; k < BK; k++) {
            float a[8], b[8];
            *(float4*)(a)     = *(float4*)(&As[k][ty * 8]);
            *(float4*)(a + 4) = *(float4*)(&As[k][ty * 8 + 4]);
            *(float4*)(b)     = *(float4*)(&Bs[k][tx * 8]);
            *(float4*)(b + 4) = *(float4*)(&Bs[k][tx * 8 + 4]);
#pragma unroll
            for (int i = 0; i < 8; i++)
#pragma unroll
                for (int j = 0; j < 8; j++) acc[i][j] += a[i] * b[j];
        }
        __syncthreads();
    }

    // Epilogue: scatter into Q/K/V [B*H][N][D]
#pragma unroll
    for (int i = 0; i < 8; i++) {
        int m = m0 + ty * 8 + i;
        int bb = m >> 11;          // /2048
        int tok = m & 2047;
#pragma unroll
        for (int j = 0; j < 8; j++) {
            int n = n0 + tx * 8 + j;
            float val = acc[i][j] + bias[n];
            int which = n >> 10;   // 0=q 1=k 2=v
            int c = n & 1023;
            int h = c >> 6;
            int d = c & 63;
            float* dst = (which == 0) ? g_q : (which == 1) ? g_k : g_v;
            dst[(((size_t)bb * H_ + h) * N_ + tok) * D_ + d] = val;
        }
    }
}

// ---------------------------------------------------------------------------
// Kernel 2: flash attention (fp32).  One CTA = (b,h) x 64-query tile.
// 256 threads. S and PV as 4x4 register tiles; online softmax; P reuses K smem.
// ---------------------------------------------------------------------------
__global__ __launch_bounds__(256) void attn_kernel()
{
    extern __shared__ float sm[];
    float* Qs = sm;               // [64][65]
    float* Ks = sm + 64 * 65;     // [64][65] -- reused for P
    float* Vs = sm + 2 * 64 * 65; // [64][64]

    const int tid = threadIdx.x;
    const int bh = blockIdx.x;         // b*16 + h
    const int r0 = blockIdx.y * 64;
    const int tr = tid >> 4;           // 0..15 (row group of 4)
    const int tc = tid & 15;           // 0..15 (col group)

    const float* Qg = g_q + (size_t)bh * N_ * D_;
    const float* Kg = g_k + (size_t)bh * N_ * D_;
    const float* Vg = g_v + (size_t)bh * N_ * D_;

    // Load Q tile (64 x 64) into padded smem
#pragma unroll
    for (int i = 0; i < 4; i++) {
        int s = tid * 4 + i;           // 0..1023 float4 slots
        int r = s >> 4, d4 = s & 15;
        float4 v = *(const float4*)(Qg + (size_t)(r0 + r) * D_ + d4 * 4);
        Qs[r * 65 + d4 * 4 + 0] = v.x;
        Qs[r * 65 + d4 * 4 + 1] = v.y;
        Qs[r * 65 + d4 * 4 + 2] = v.z;
        Qs[r * 65 + d4 * 4 + 3] = v.w;
    }

    float m_old[4], lsum[4], o[4][4];
#pragma unroll
    for (int i = 0; i < 4; i++) {
        m_old[i] = -CUDART_INF_F;
        lsum[i] = 0.f;
#pragma unroll
        for (int j = 0; j < 4; j++) o[i][j] = 0.f;
    }

    for (int kt = 0; kt < N_ / 64; kt++) {
        // Load K and V tiles
#pragma unroll
        for (int i = 0; i < 4; i++) {
            int s = tid * 4 + i;
            int r = s >> 4, d4 = s & 15;
            float4 kv = *(const float4*)(Kg + (size_t)(kt * 64 + r) * D_ + d4 * 4);
            Ks[r * 65 + d4 * 4 + 0] = kv.x;
            Ks[r * 65 + d4 * 4 + 1] = kv.y;
            Ks[r * 65 + d4 * 4 + 2] = kv.z;
            Ks[r * 65 + d4 * 4 + 3] = kv.w;
            float4 vv = *(const float4*)(Vg + (size_t)(kt * 64 + r) * D_ + d4 * 4);
            *(float4*)(&Vs[r * 64 + d4 * 4]) = vv;
        }
        __syncthreads();

        // S = Q K^T for this thread's 4x4 tile: rows tr*4+i, cols tc+16*j
        float s_[4][4];
#pragma unroll
        for (int i = 0; i < 4; i++)
#pragma unroll
            for (int j = 0; j < 4; j++) s_[i][j] = 0.f;

#pragma unroll 4
        for (int d = 0; d < 64; d++) {
            float q0 = Qs[(tr * 4 + 0) * 65 + d];
            float q1 = Qs[(tr * 4 + 1) * 65 + d];
            float q2 = Qs[(tr * 4 + 2) * 65 + d];
            float q3 = Qs[(tr * 4 + 3) * 65 + d];
            float k0 = Ks[(tc + 16 * 0) * 65 + d];
            float k1 = Ks[(tc + 16 * 1) * 65 + d];
            float k2 = Ks[(tc + 16 * 2) * 65 + d];
            float k3 = Ks[(tc + 16 * 3) * 65 + d];
            s_[0][0] += q0 * k0; s_[0][1] += q0 * k1; s_[0][2] += q0 * k2; s_[0][3] += q0 * k3;
            s_[1][0] += q1 * k0; s_[1][1] += q1 * k1; s_[1][2] += q1 * k2; s_[1][3] += q1 * k3;
            s_[2][0] += q2 * k0; s_[2][1] += q2 * k1; s_[2][2] += q2 * k2; s_[2][3] += q2 * k3;
            s_[3][0] += q3 * k0; s_[3][1] += q3 * k1; s_[3][2] += q3 * k2; s_[3][3] += q3 * k3;
        }

        // Online softmax: reduce over the 16 lanes sharing tr (16-aligned groups)
        float alpha[4];
#pragma unroll
        for (int i = 0; i < 4; i++) {
            float mloc = s_[i][0];
#pragma unroll
            for (int j = 1; j < 4; j++) mloc = fmaxf(mloc, s_[i][j]);
            mloc *= SCALE_;
#pragma unroll
            for (int mask = 1; mask <= 8; mask <<= 1)
                mloc = fmaxf(mloc, __shfl_xor_sync(0xffffffffu, mloc, mask));
            float mnew = fmaxf(m_old[i], mloc);
            alpha[i] = __expf(m_old[i] - mnew);
            float ll = 0.f;
#pragma unroll
            for (int j = 0; j < 4; j++) {
                s_[i][j] = __expf(s_[i][j] * SCALE_ - mnew);   // now P
                ll += s_[i][j];
            }
#pragma unroll
            for (int mask = 1; mask <= 8; mask <<= 1)
                ll += __shfl_xor_sync(0xffffffffu, ll, mask);
            lsum[i] = lsum[i] * alpha[i] + ll;
            m_old[i] = mnew;
#pragma unroll
            for (int jj = 0; jj < 4; jj++) o[i][jj] *= alpha[i];
        }

        __syncthreads();   // everyone done reading Ks
        // Write P into the K buffer (each thread writes its own 16 slots)
#pragma unroll
        for (int i = 0; i < 4; i++)
#pragma unroll
            for (int j = 0; j < 4; j++)
                Ks[(tr * 4 + i) * 65 + (tc + 16 * j)] = s_[i][j];
        __syncthreads();

        // O += P V : rows tr*4+i, cols tc+16*jj
#pragma unroll 4
        for (int j = 0; j < 64; j++) {
            float p0 = Ks[(tr * 4 + 0) * 65 + j];
            float p1 = Ks[(tr * 4 + 1) * 65 + j];
            float p2 = Ks[(tr * 4 + 2) * 65 + j];
            float p3 = Ks[(tr * 4 + 3) * 65 + j];
            float v0 = Vs[j * 64 + tc + 16 * 0];
            float v1 = Vs[j * 64 + tc + 16 * 1];
            float v2 = Vs[j * 64 + tc + 16 * 2];
            float v3 = Vs[j * 64 + tc + 16 * 3];
            o[0][0] += p0 * v0; o[0][1] += p0 * v1; o[0][2] += p0 * v2; o[0][3] += p0 * v3;
            o[1][0] += p1 * v0; o[1][1] += p1 * v1; o[1][2] += p1 * v2; o[1][3] += p1 * v3;
            o[2][0] += p2 * v0; o[2][1] += p2 * v1; o[2][2] += p2 * v2; o[2][3] += p2 * v3;
            o[3][0] += p3 * v0; o[3][1] += p3 * v1; o[3][2] += p3 * v2; o[3][3] += p3 * v3;
        }
        __syncthreads();   // before next tile overwrites Ks/Vs
    }

    // Epilogue: write to g_att in [B][N][C] layout
    const int b = bh >> 4;
    const int h = bh & 15;
#pragma unroll
    for (int i = 0; i < 4; i++) {
        float inv = 1.0f / lsum[i];
        int row = r0 + tr * 4 + i;
#pragma unroll
        for (int jj = 0; jj < 4; jj++) {
            g_att[((size_t)b * N_ + row) * C_ + h * 64 + tc + 16 * jj] = o[i][jj] * inv;
        }
    }
}

// ---------------------------------------------------------------------------
// Kernel 3: output projection.  g_att[8192,1024] @ Wp[1024,1024] + bias -> out
// ---------------------------------------------------------------------------
__global__ __launch_bounds__(256) void proj_gemm_kernel(
    const float* __restrict__ W, const float* __restrict__ bias,
    float* __restrict__ out)
{
    const int BK = 16;
    __shared__ float As[16][128];
    __shared__ float Bs[16][128];

    const int tid = threadIdx.x;
    const int m0 = blockIdx.y * 128;
    const int n0 = blockIdx.x * 128;
    const int tx = tid & 15;
    const int ty = tid >> 4;

    float acc[8][8];
#pragma unroll
    for (int i = 0; i < 8; i++)
#pragma unroll
        for (int j = 0; j < 8; j++) acc[i][j] = 0.f;

    for (int k0 = 0; k0 < C_; k0 += BK) {
#pragma unroll
        for (int i = 0; i < 2; i++) {
            int s = tid * 2 + i;
            int m = s >> 2, kq = s & 3;
            float4 v = *(const float4*)(g_att + (size_t)(m0 + m) * C_ + k0 + kq * 4);
            As[kq * 4 + 0][m] = v.x;
            As[kq * 4 + 1][m] = v.y;
            As[kq * 4 + 2][m] = v.z;
            As[kq * 4 + 3][m] = v.w;
        }
#pragma unroll
        for (int i = 0; i < 2; i++) {
            int s = tid * 2 + i;
            int k = s >> 5, n4 = s & 31;
            *(float4*)(&Bs[k][n4 * 4]) =
                *(const float4*)(W + (size_t)(k0 + k) * C_ + n0 + n4 * 4);
        }
        __syncthreads();

#pragma unroll
        for (int k = 0; k < BK; k++) {
            float a[8], b[8];
            *(float4*)(a)     = *(float4*)(&As[k][ty * 8]);
            *(float4*)(a + 4) = *(float4*)(&As[k][ty * 8 + 4]);
            *(float4*)(b)     = *(float4*)(&Bs[k][tx * 8]);
            *(float4*)(b + 4) = *(float4*)(&Bs[k][tx * 8 + 4]);
#pragma unroll
            for (int i = 0; i < 8; i++)
#pragma unroll
                for (int j = 0; j < 8; j++) acc[i][j] += a[i] * b[j];
        }
        __syncthreads();
    }

#pragma unroll
    for (int i = 0; i < 8; i++) {
        int m = m0 + ty * 8 + i;
#pragma unroll
        for (int j = 0; j < 8; j++) {
            int n = n0 + tx * 8 + j;
            out[(size_t)m * C_ + n] = acc[i][j] + bias[n];
        }
    }
}

// ---------------------------------------------------------------------------
extern "C" void kernel_launch(void* const* d_in, const int* in_sizes, int n_in,
                              void* d_out, int out_size)
{
    const float* x      = (const float*)d_in[0];
    const float* w_qkv  = (const float*)d_in[1];
    const float* b_qkv  = (const float*)d_in[2];
    const float* w_proj = (const float*)d_in[3];
    const float* b_proj = (const float*)d_in[4];
    float* out = (float*)d_out;

    // QKV GEMM: M=8192, N=3072
    {
        dim3 grid(3 * C_ / 128, (B_ * N_) / 128);
        qkv_gemm_kernel<<<grid, 256>>>(x, w_qkv, b_qkv);
    }

    // Attention: grid = (B*H, N/64)
    {
        const int smem = (64 * 65 * 2 + 64 * 64) * sizeof(float);  // 49664 B
        cudaFuncSetAttribute(attn_kernel,
                             cudaFuncAttributeMaxDynamicSharedMemorySize, smem);
        dim3 grid(B_ * H_, N_ / 64);
        attn_kernel<<<grid, 256, smem>>>();
    }

    // Projection GEMM: M=8192, N=1024
    {
        dim3 grid(C_ / 128, (B_ * N_) / 128);
        proj_gemm_kernel<<<grid, 256>>>(w_proj, b_proj, out);
    }
}

// round 4
// speedup vs baseline: 2.1736x; 2.1736x over previous
#include <cuda_runtime.h>
#include <cuda_bf16.h>
#include <math_constants.h>
#include <cstdint>

// Problem constants
#define B_ 4
#define N_ 2048
#define C_ 1024
#define H_ 16
#define D_ 64
#define SCALE_ 0.125f   // 1/sqrt(64)

// ---------------------------------------------------------------------------
// Scratch (device globals: allocation-free)
// ---------------------------------------------------------------------------
__device__ float g_q[B_ * H_ * N_ * D_];     // [B*H][N][D] fp32
__device__ float g_k[B_ * H_ * N_ * D_];
__device__ float g_v[B_ * H_ * N_ * D_];
__device__ float g_att[B_ * N_ * C_];        // [B][N][C] fp32

// bf16 hi/lo split operands
__device__ __nv_bfloat16 g_xhi[B_ * N_ * C_];        // X split [8192][1024]
__device__ __nv_bfloat16 g_xlo[B_ * N_ * C_];
__device__ __nv_bfloat16 g_ahi[B_ * N_ * C_];        // att split [8192][1024]
__device__ __nv_bfloat16 g_alo[B_ * N_ * C_];
__device__ __nv_bfloat16 g_wqkv_hi[3 * C_ * C_];     // W_qkv^T split [3072][1024]
__device__ __nv_bfloat16 g_wqkv_lo[3 * C_ * C_];
__device__ __nv_bfloat16 g_wp_hi[C_ * C_];           // W_proj^T split [1024][1024]
__device__ __nv_bfloat16 g_wp_lo[C_ * C_];

// ---------------------------------------------------------------------------
// PTX helpers (sm_103 base ISA — no tcgen05 in this toolchain)
// ---------------------------------------------------------------------------
__device__ __forceinline__ uint32_t smem_to_u32(const void* p) {
    uint32_t a;
    asm("{ .reg .u64 t; cvta.to.shared.u64 t, %1; cvt.u32.u64 %0, t; }"
        : "=r"(a) : "l"(p));
    return a;
}

#define CP_ASYNC16(saddr, gptr) \
    asm volatile("cp.async.cg.shared.global [%0], [%1], 16;" \
                 :: "r"(saddr), "l"(gptr) : "memory")
#define CP_COMMIT() asm volatile("cp.async.commit_group;" ::: "memory")
#define CP_WAIT1()  asm volatile("cp.async.wait_group 1;" ::: "memory")
#define CP_WAIT0()  asm volatile("cp.async.wait_group 0;" ::: "memory")

#define LDSM_X4(r0, r1, r2, r3, addr) \
    asm volatile("ldmatrix.sync.aligned.m8n8.x4.shared.b16 {%0,%1,%2,%3}, [%4];" \
                 : "=r"(r0), "=r"(r1), "=r"(r2), "=r"(r3) : "r"(addr))

#define MMA16816(d, a, b0, b1) \
    asm volatile("mma.sync.aligned.m16n8k16.row.col.f32.bf16.bf16.f32 " \
                 "{%0,%1,%2,%3}, {%4,%5,%6,%7}, {%8,%9}, {%0,%1,%2,%3};" \
                 : "+f"((d)[0]), "+f"((d)[1]), "+f"((d)[2]), "+f"((d)[3]) \
                 : "r"((a)[0]), "r"((a)[1]), "r"((a)[2]), "r"((a)[3]), \
                   "r"(b0), "r"(b1))

// ---------------------------------------------------------------------------
// fp32 -> bf16 hi/lo split (no transpose).  DST 0: x -> g_xhi/g_xlo,
// DST 1: g_att -> g_ahi/g_alo.
// ---------------------------------------------------------------------------
template<int DST>
__global__ __launch_bounds__(256) void split_kernel(const float* __restrict__ in, int n4)
{
    const float* src = (DST == 0) ? in : g_att;
    __nv_bfloat16* hi = (DST == 0) ? g_xhi : g_ahi;
    __nv_bfloat16* lo = (DST == 0) ? g_xlo : g_alo;
    int i = blockIdx.x * 256 + threadIdx.x;
    if (i >= n4) return;
    float4 v = ((const float4*)src)[i];
    union U { __nv_bfloat16 b[4]; uint2 u; } Hh, Ll;
    float vv[4] = {v.x, v.y, v.z, v.w};
#pragma unroll
    for (int j = 0; j < 4; j++) {
        __nv_bfloat16 h = __float2bfloat16(vv[j]);
        float hf = __bfloat162float(h);
        Hh.b[j] = h;
        Ll.b[j] = __float2bfloat16(vv[j] - hf);
    }
    ((uint2*)hi)[i] = Hh.u;
    ((uint2*)lo)[i] = Ll.u;
}

// ---------------------------------------------------------------------------
// fp32 W[K=1024][Ncols] -> transposed bf16 hi/lo [Ncols][1024]
// ---------------------------------------------------------------------------
template<int DST>
__global__ __launch_bounds__(256) void splitT_kernel(const float* __restrict__ in, int Ccols)
{
    __nv_bfloat16* hi = (DST == 0) ? g_wqkv_hi : g_wp_hi;
    __nv_bfloat16* lo = (DST == 0) ? g_wqkv_lo : g_wp_lo;
    __shared__ float t[32][33];
    int tx = threadIdx.x & 31;
    int ty = threadIdx.x >> 5;       // 0..7
    int n_base = blockIdx.x * 32;
    int k_base = blockIdx.y * 32;
#pragma unroll
    for (int i = 0; i < 4; i++) {
        int k = k_base + ty + i * 8;
        t[ty + i * 8][tx] = in[(size_t)k * Ccols + n_base + tx];
    }
    __syncthreads();
#pragma unroll
    for (int i = 0; i < 4; i++) {
        int nn = n_base + ty + i * 8;
        int k = k_base + tx;
        float v = t[tx][ty + i * 8];
        __nv_bfloat16 h = __float2bfloat16(v);
        float hf = __bfloat162float(h);
        hi[(size_t)nn * C_ + k] = h;
        lo[(size_t)nn * C_ + k] = __float2bfloat16(v - hf);
    }
}

// ---------------------------------------------------------------------------
// HMMA bf16-split GEMM.  C tile 128x128 per CTA, BK=32, double-buffered
// cp.async pipeline.  8 warps, each 32x64 (2x8 m16n8 tiles), 3 MMAs per
// logical MMA (hi*hi + hi*lo + lo*hi).
// MODE 0: X @ Wqkv^T -> scatter fp32 into g_q/g_k/g_v (+bias)
// MODE 1: att @ Wproj^T -> d_out (+bias)
// ---------------------------------------------------------------------------
#define GBK 32
#define LDA 40                        // padded row stride (bf16 elems)
#define MAT_ELEMS (128 * LDA)         // 5120 elems per matrix tile
#define STAGE_ELEMS (4 * MAT_ELEMS)   // Ahi, Alo, Bhi, Blo
#define SMEM_GEMM (2 * STAGE_ELEMS * 2)   // bytes = 81920

template<int MODE>
__global__ __launch_bounds__(256) void mma_gemm_kernel(
    const float* __restrict__ bias, float* __restrict__ outp)
{
    const __nv_bfloat16* Ahi = (MODE == 0) ? g_xhi : g_ahi;
    const __nv_bfloat16* Alo = (MODE == 0) ? g_xlo : g_alo;
    const __nv_bfloat16* Bhi = (MODE == 0) ? g_wqkv_hi : g_wp_hi;
    const __nv_bfloat16* Blo = (MODE == 0) ? g_wqkv_lo : g_wp_lo;

    extern __shared__ __nv_bfloat16 sm[];
    const uint32_t sbase = smem_to_u32(sm);
    const int tid = threadIdx.x;
    const int wid = tid >> 5, lane = tid & 31;
    const int warp_m = wid & 3;          // 4 warps over M
    const int warp_n = wid >> 2;         // 2 warps over N
    const int m0 = blockIdx.y * 128;
    const int n0 = blockIdx.x * 128;

    float acc[2][8][4];
#pragma unroll
    for (int a = 0; a < 2; a++)
#pragma unroll
        for (int b = 0; b < 8; b++)
#pragma unroll
            for (int c = 0; c < 4; c++) acc[a][b][c] = 0.f;

    const int row = tid >> 2;            // 0..63 handled twice (tid, tid+256)
    const int un = tid & 3;

    // ---- stage loader: 8 cp.async of 16B per thread ----
    auto load_stage = [&](int s) {
        const int buf = s & 1;
        const int k0 = s * GBK;
        const uint32_t sb = sbase + (uint32_t)buf * STAGE_ELEMS * 2;
        const __nv_bfloat16* srcs[4] = {Ahi, Alo, Bhi, Blo};
#pragma unroll
        for (int mat = 0; mat < 4; mat++) {
            const int rbase = (mat < 2) ? m0 : n0;
            const __nv_bfloat16* src = srcs[mat];
#pragma unroll
            for (int i = 0; i < 2; i++) {
                int r = row + i * 64;
                uint32_t so = sb + (uint32_t)(mat * MAT_ELEMS + r * LDA + un * 8) * 2;
                const void* gp = src + (size_t)(rbase + r) * C_ + k0 + un * 8;
                CP_ASYNC16(so, gp);
            }
        }
        CP_COMMIT();
    };

    constexpr int NS = C_ / GBK;   // 32 stages
    load_stage(0);

    for (int s = 0; s < NS; s++) {
        if (s + 1 < NS) { load_stage(s + 1); CP_WAIT1(); }
        else            { CP_WAIT0(); }
        __syncthreads();

        const uint32_t sb = sbase + (uint32_t)(s & 1) * STAGE_ELEMS * 2;
        const int lrow = lane & 15;
        const int lk = (lane >> 4) * 8;

#pragma unroll
        for (int kk = 0; kk < GBK; kk += 16) {
            uint32_t ah[2][4], al[2][4], bh[4][4], bl[4][4];
#pragma unroll
            for (int mt = 0; mt < 2; mt++) {
                uint32_t off = (uint32_t)((warp_m * 32 + mt * 16 + lrow) * LDA + kk + lk) * 2;
                LDSM_X4(ah[mt][0], ah[mt][1], ah[mt][2], ah[mt][3], sb + off);
                LDSM_X4(al[mt][0], al[mt][1], al[mt][2], al[mt][3],
                        sb + (uint32_t)MAT_ELEMS * 2 + off);
            }
#pragma unroll
            for (int np = 0; np < 4; np++) {
                uint32_t off = (uint32_t)((warp_n * 64 + np * 16 + lrow) * LDA + kk + lk) * 2;
                LDSM_X4(bh[np][0], bh[np][1], bh[np][2], bh[np][3],
                        sb + (uint32_t)(2 * MAT_ELEMS) * 2 + off);
                LDSM_X4(bl[np][0], bl[np][1], bl[np][2], bl[np][3],
                        sb + (uint32_t)(3 * MAT_ELEMS) * 2 + off);
            }
#pragma unroll
            for (int mt = 0; mt < 2; mt++) {
#pragma unroll
                for (int np = 0; np < 4; np++) {
#pragma unroll
                    for (int sel = 0; sel < 2; sel++) {
                        int nt = np * 2 + sel;
                        MMA16816(acc[mt][nt], ah[mt], bh[np][sel], bh[np][2 + sel]);
                        MMA16816(acc[mt][nt], ah[mt], bl[np][sel], bl[np][2 + sel]);
                        MMA16816(acc[mt][nt], al[mt], bh[np][sel], bh[np][2 + sel]);
                    }
                }
            }
        }
        __syncthreads();
    }

    // ---- epilogue ----
#pragma unroll
    for (int mt = 0; mt < 2; mt++) {
#pragma unroll
        for (int nt = 0; nt < 8; nt++) {
            int r = m0 + warp_m * 32 + mt * 16 + (lane >> 2);
            int c = n0 + warp_n * 64 + nt * 8 + (lane & 3) * 2;
            float b0 = bias[c], b1 = bias[c + 1];
            float2 v0 = make_float2(acc[mt][nt][0] + b0, acc[mt][nt][1] + b1);
            float2 v1 = make_float2(acc[mt][nt][2] + b0, acc[mt][nt][3] + b1);
            if (MODE == 0) {
                int bb = r >> 11, tok = r & 2047;
                int which = c >> 10, ch = c & 1023, h = ch >> 6, d0 = ch & 63;
                float* dst = (which == 0) ? g_q : (which == 1) ? g_k : g_v;
                size_t base = (((size_t)bb * H_ + h) * N_ + tok) * D_ + d0;
                *(float2*)(dst + base) = v0;
                *(float2*)(dst + base + 8 * D_) = v1;
            } else {
                *(float2*)(outp + (size_t)r * C_ + c) = v0;
                *(float2*)(outp + (size_t)(r + 8) * C_ + c) = v1;
            }
        }
    }
}

// ---------------------------------------------------------------------------
// Kernel 2: flash attention (fp32) — unchanged (known correct).
// ---------------------------------------------------------------------------
__global__ __launch_bounds__(256) void attn_kernel()
{
    extern __shared__ float smf[];
    float* Qs = smf;               // [64][65]
    float* Ks = smf + 64 * 65;     // [64][65] -- reused for P
    float* Vs = smf + 2 * 64 * 65; // [64][64]

    const int tid = threadIdx.x;
    const int bh = blockIdx.x;
    const int r0 = blockIdx.y * 64;
    const int tr = tid >> 4;
    const int tc = tid & 15;

    const float* Qg = g_q + (size_t)bh * N_ * D_;
    const float* Kg = g_k + (size_t)bh * N_ * D_;
    const float* Vg = g_v + (size_t)bh * N_ * D_;

#pragma unroll
    for (int i = 0; i < 4; i++) {
        int s = tid * 4 + i;
        int r = s >> 4, d4 = s & 15;
        float4 v = *(const float4*)(Qg + (size_t)(r0 + r) * D_ + d4 * 4);
        Qs[r * 65 + d4 * 4 + 0] = v.x;
        Qs[r * 65 + d4 * 4 + 1] = v.y;
        Qs[r * 65 + d4 * 4 + 2] = v.z;
        Qs[r * 65 + d4 * 4 + 3] = v.w;
    }

    float m_old[4], lsum[4], o[4][4];
#pragma unroll
    for (int i = 0; i < 4; i++) {
        m_old[i] = -CUDART_INF_F;
        lsum[i] = 0.f;
#pragma unroll
        for (int j = 0; j < 4; j++) o[i][j] = 0.f;
    }

    for (int kt = 0; kt < N_ / 64; kt++) {
#pragma unroll
        for (int i = 0; i < 4; i++) {
            int s = tid * 4 + i;
            int r = s >> 4, d4 = s & 15;
            float4 kv = *(const float4*)(Kg + (size_t)(kt * 64 + r) * D_ + d4 * 4);
            Ks[r * 65 + d4 * 4 + 0] = kv.x;
            Ks[r * 65 + d4 * 4 + 1] = kv.y;
            Ks[r * 65 + d4 * 4 + 2] = kv.z;
            Ks[r * 65 + d4 * 4 + 3] = kv.w;
            float4 vv = *(const float4*)(Vg + (size_t)(kt * 64 + r) * D_ + d4 * 4);
            *(float4*)(&Vs[r * 64 + d4 * 4]) = vv;
        }
        __syncthreads();

        float s_[4][4];
#pragma unroll
        for (int i = 0; i < 4; i++)
#pragma unroll
            for (int j = 0; j < 4; j++) s_[i][j] = 0.f;

#pragma unroll 4
        for (int d = 0; d < 64; d++) {
            float q0 = Qs[(tr * 4 + 0) * 65 + d];
            float q1 = Qs[(tr * 4 + 1) * 65 + d];
            float q2 = Qs[(tr * 4 + 2) * 65 + d];
            float q3 = Qs[(tr * 4 + 3) * 65 + d];
            float k0 = Ks[(tc + 16 * 0) * 65 + d];
            float k1 = Ks[(tc + 16 * 1) * 65 + d];
            float k2 = Ks[(tc + 16 * 2) * 65 + d];
            float k3 = Ks[(tc + 16 * 3) * 65 + d];
            s_[0][0] += q0 * k0; s_[0][1] += q0 * k1; s_[0][2] += q0 * k2; s_[0][3] += q0 * k3;
            s_[1][0] += q1 * k0; s_[1][1] += q1 * k1; s_[1][2] += q1 * k2; s_[1][3] += q1 * k3;
            s_[2][0] += q2 * k0; s_[2][1] += q2 * k1; s_[2][2] += q2 * k2; s_[2][3] += q2 * k3;
            s_[3][0] += q3 * k0; s_[3][1] += q3 * k1; s_[3][2] += q3 * k2; s_[3][3] += q3 * k3;
        }

        float alpha[4];
#pragma unroll
        for (int i = 0; i < 4; i++) {
            float mloc = s_[i][0];
#pragma unroll
            for (int j = 1; j < 4; j++) mloc = fmaxf(mloc, s_[i][j]);
            mloc *= SCALE_;
#pragma unroll
            for (int mask = 1; mask <= 8; mask <<= 1)
                mloc = fmaxf(mloc, __shfl_xor_sync(0xffffffffu, mloc, mask));
            float mnew = fmaxf(m_old[i], mloc);
            alpha[i] = __expf(m_old[i] - mnew);
            float ll = 0.f;
#pragma unroll
            for (int j = 0; j < 4; j++) {
                s_[i][j] = __expf(s_[i][j] * SCALE_ - mnew);
                ll += s_[i][j];
            }
#pragma unroll
            for (int mask = 1; mask <= 8; mask <<= 1)
                ll += __shfl_xor_sync(0xffffffffu, ll, mask);
            lsum[i] = lsum[i] * alpha[i] + ll;
            m_old[i] = mnew;
#pragma unroll
            for (int jj = 0; jj < 4; jj++) o[i][jj] *= alpha[i];
        }

        __syncthreads();
#pragma unroll
        for (int i = 0; i < 4; i++)
#pragma unroll
            for (int j = 0; j < 4; j++)
                Ks[(tr * 4 + i) * 65 + (tc + 16 * j)] = s_[i][j];
        __syncthreads();

#pragma unroll 4
        for (int j = 0; j < 64; j++) {
            float p0 = Ks[(tr * 4 + 0) * 65 + j];
            float p1 = Ks[(tr * 4 + 1) * 65 + j];
            float p2 = Ks[(tr * 4 + 2) * 65 + j];
            float p3 = Ks[(tr * 4 + 3) * 65 + j];
            float v0 = Vs[j * 64 + tc + 16 * 0];
            float v1 = Vs[j * 64 + tc + 16 * 1];
            float v2 = Vs[j * 64 + tc + 16 * 2];
            float v3 = Vs[j * 64 + tc + 16 * 3];
            o[0][0] += p0 * v0; o[0][1] += p0 * v1; o[0][2] += p0 * v2; o[0][3] += p0 * v3;
            o[1][0] += p1 * v0; o[1][1] += p1 * v1; o[1][2] += p1 * v2; o[1][3] += p1 * v3;
            o[2][0] += p2 * v0; o[2][1] += p2 * v1; o[2][2] += p2 * v2; o[2][3] += p2 * v3;
            o[3][0] += p3 * v0; o[3][1] += p3 * v1; o[3][2] += p3 * v2; o[3][3] += p3 * v3;
        }
        __syncthreads();
    }

    const int b = bh >> 4;
    const int h = bh & 15;
#pragma unroll
    for (int i = 0; i < 4; i++) {
        float inv = 1.0f / lsum[i];
        int rw = r0 + tr * 4 + i;
#pragma unroll
        for (int jj = 0; jj < 4; jj++) {
            g_att[((size_t)b * N_ + rw) * C_ + h * 64 + tc + 16 * jj] = o[i][jj] * inv;
        }
    }
}

// ---------------------------------------------------------------------------
extern "C" void kernel_launch(void* const* d_in, const int* in_sizes, int n_in,
                              void* d_out, int out_size)
{
    const float* x      = (const float*)d_in[0];
    const float* w_qkv  = (const float*)d_in[1];
    const float* b_qkv  = (const float*)d_in[2];
    const float* w_proj = (const float*)d_in[3];
    const float* b_proj = (const float*)d_in[4];
    float* out = (float*)d_out;

    cudaFuncSetAttribute(mma_gemm_kernel<0>,
                         cudaFuncAttributeMaxDynamicSharedMemorySize, SMEM_GEMM);
    cudaFuncSetAttribute(mma_gemm_kernel<1>,
                         cudaFuncAttributeMaxDynamicSharedMemorySize, SMEM_GEMM);

    // 1. Split conversions of X and both weight matrices (W also transposed)
    {
        int n4 = B_ * N_ * C_ / 4;           // 2,097,152
        split_kernel<0><<<(n4 + 255) / 256, 256>>>(x, n4);
        dim3 g1(3 * C_ / 32, C_ / 32);       // (96, 32)
        splitT_kernel<0><<<g1, 256>>>(w_qkv, 3 * C_);
        dim3 g2(C_ / 32, C_ / 32);           // (32, 32)
        splitT_kernel<1><<<g2, 256>>>(w_proj, C_);
    }

    // 2. QKV GEMM on tensor cores (HMMA) -> g_q/g_k/g_v (fp32)
    {
        dim3 grid(3 * C_ / 128, (B_ * N_) / 128);  // (24, 64)
        mma_gemm_kernel<0><<<grid, 256, SMEM_GEMM>>>(b_qkv, nullptr);
    }

    // 3. Flash attention (fp32) -> g_att
    {
        const int smem = (64 * 65 * 2 + 64 * 64) * sizeof(float);
        cudaFuncSetAttribute(attn_kernel,
                             cudaFuncAttributeMaxDynamicSharedMemorySize, smem);
        dim3 grid(B_ * H_, N_ / 64);
        attn_kernel<<<grid, 256, smem>>>();
    }

    // 4. Split attention output, then projection GEMM -> out
    {
        int n4 = B_ * N_ * C_ / 4;
        split_kernel<1><<<(n4 + 255) / 256, 256>>>(nullptr, n4);
        dim3 grid(C_ / 128, (B_ * N_) / 128);      // (8, 64)
        mma_gemm_kernel<1><<<grid, 256, SMEM_GEMM>>>(b_proj, out);
    }
}

// round 5
// speedup vs baseline: 4.9942x; 2.2977x over previous
#include <cuda_runtime.h>
#include <cuda_bf16.h>
#include <math_constants.h>
#include <cstdint>

// Problem constants
#define B_ 4
#define N_ 2048
#define C_ 1024
#define H_ 16
#define D_ 64
#define SCALE_ 0.125f   // 1/sqrt(64)

// ---------------------------------------------------------------------------
// Scratch (device globals: allocation-free)
// ---------------------------------------------------------------------------
__device__ __nv_bfloat16 g_qhi[B_ * H_ * N_ * D_];   // q pre-scaled by 0.125
__device__ __nv_bfloat16 g_qlo[B_ * H_ * N_ * D_];
__device__ __nv_bfloat16 g_khi[B_ * H_ * N_ * D_];
__device__ __nv_bfloat16 g_klo[B_ * H_ * N_ * D_];
__device__ __nv_bfloat16 g_vhi[B_ * H_ * N_ * D_];
__device__ __nv_bfloat16 g_vlo[B_ * H_ * N_ * D_];

__device__ __nv_bfloat16 g_xhi[B_ * N_ * C_];        // X split [8192][1024]
__device__ __nv_bfloat16 g_xlo[B_ * N_ * C_];
__device__ __nv_bfloat16 g_ahi[B_ * N_ * C_];        // attention out split
__device__ __nv_bfloat16 g_alo[B_ * N_ * C_];
__device__ __nv_bfloat16 g_wqkv_hi[3 * C_ * C_];     // W_qkv^T split [3072][1024]
__device__ __nv_bfloat16 g_wqkv_lo[3 * C_ * C_];
__device__ __nv_bfloat16 g_wp_hi[C_ * C_];           // W_proj^T split [1024][1024]
__device__ __nv_bfloat16 g_wp_lo[C_ * C_];

// ---------------------------------------------------------------------------
// PTX helpers (sm_103 base ISA)
// ---------------------------------------------------------------------------
__device__ __forceinline__ uint32_t smem_to_u32(const void* p) {
    uint32_t a;
    asm("{ .reg .u64 t; cvta.to.shared.u64 t, %1; cvt.u32.u64 %0, t; }"
        : "=r"(a) : "l"(p));
    return a;
}

#define CP_ASYNC16(saddr, gptr) \
    asm volatile("cp.async.cg.shared.global [%0], [%1], 16;" \
                 :: "r"(saddr), "l"(gptr) : "memory")
#define CP_COMMIT() asm volatile("cp.async.commit_group;" ::: "memory")
#define CP_WAIT1()  asm volatile("cp.async.wait_group 1;" ::: "memory")
#define CP_WAIT0()  asm volatile("cp.async.wait_group 0;" ::: "memory")

#define LDSM_X4(r0, r1, r2, r3, addr) \
    asm volatile("ldmatrix.sync.aligned.m8n8.x4.shared.b16 {%0,%1,%2,%3}, [%4];" \
                 : "=r"(r0), "=r"(r1), "=r"(r2), "=r"(r3) : "r"(addr))
#define LDSM_X4_T(r0, r1, r2, r3, addr) \
    asm volatile("ldmatrix.sync.aligned.m8n8.x4.trans.shared.b16 {%0,%1,%2,%3}, [%4];" \
                 : "=r"(r0), "=r"(r1), "=r"(r2), "=r"(r3) : "r"(addr))

#define MMA16816(d, a, b0, b1) \
    asm volatile("mma.sync.aligned.m16n8k16.row.col.f32.bf16.bf16.f32 " \
                 "{%0,%1,%2,%3}, {%4,%5,%6,%7}, {%8,%9}, {%0,%1,%2,%3};" \
                 : "+f"((d)[0]), "+f"((d)[1]), "+f"((d)[2]), "+f"((d)[3]) \
                 : "r"((a)[0]), "r"((a)[1]), "r"((a)[2]), "r"((a)[3]), \
                   "r"(b0), "r"(b1))

// split f0,f1 into bf16 hi/lo packed pairs
__device__ __forceinline__ void pack_split(float f0, float f1,
                                           uint32_t& hi, uint32_t& lo) {
    __nv_bfloat16 h0 = __float2bfloat16(f0), h1 = __float2bfloat16(f1);
    __nv_bfloat162 Hh; Hh.x = h0; Hh.y = h1;
    __nv_bfloat162 Ll;
    Ll.x = __float2bfloat16(f0 - __bfloat162float(h0));
    Ll.y = __float2bfloat16(f1 - __bfloat162float(h1));
    hi = *(uint32_t*)&Hh;
    lo = *(uint32_t*)&Ll;
}
__device__ __forceinline__ void split_store2(__nv_bfloat16* hi, __nv_bfloat16* lo,
                                             size_t idx, float f0, float f1) {
    uint32_t uh, ul;
    pack_split(f0, f1, uh, ul);
    *(uint32_t*)(hi + idx) = uh;
    *(uint32_t*)(lo + idx) = ul;
}

// ---------------------------------------------------------------------------
// fp32 x -> bf16 hi/lo split
// ---------------------------------------------------------------------------
__global__ __launch_bounds__(256) void split_kernel(const float* __restrict__ in, int n4)
{
    int i = blockIdx.x * 256 + threadIdx.x;
    if (i >= n4) return;
    float4 v = ((const float4*)in)[i];
    union U { __nv_bfloat16 b[4]; uint2 u; } Hh, Ll;
    float vv[4] = {v.x, v.y, v.z, v.w};
#pragma unroll
    for (int j = 0; j < 4; j++) {
        __nv_bfloat16 h = __float2bfloat16(vv[j]);
        Hh.b[j] = h;
        Ll.b[j] = __float2bfloat16(vv[j] - __bfloat162float(h));
    }
    ((uint2*)g_xhi)[i] = Hh.u;
    ((uint2*)g_xlo)[i] = Ll.u;
}

// ---------------------------------------------------------------------------
// fp32 W[K=1024][Ncols] -> transposed bf16 hi/lo [Ncols][1024]
// ---------------------------------------------------------------------------
template<int DST>
__global__ __launch_bounds__(256) void splitT_kernel(const float* __restrict__ in, int Ccols)
{
    __nv_bfloat16* hi = (DST == 0) ? g_wqkv_hi : g_wp_hi;
    __nv_bfloat16* lo = (DST == 0) ? g_wqkv_lo : g_wp_lo;
    __shared__ float t[32][33];
    int tx = threadIdx.x & 31;
    int ty = threadIdx.x >> 5;
    int n_base = blockIdx.x * 32;
    int k_base = blockIdx.y * 32;
#pragma unroll
    for (int i = 0; i < 4; i++) {
        int k = k_base + ty + i * 8;
        t[ty + i * 8][tx] = in[(size_t)k * Ccols + n_base + tx];
    }
    __syncthreads();
#pragma unroll
    for (int i = 0; i < 4; i++) {
        int nn = n_base + ty + i * 8;
        int k = k_base + tx;
        float v = t[tx][ty + i * 8];
        __nv_bfloat16 h = __float2bfloat16(v);
        hi[(size_t)nn * C_ + k] = h;
        lo[(size_t)nn * C_ + k] = __float2bfloat16(v - __bfloat162float(h));
    }
}

// ---------------------------------------------------------------------------
// HMMA bf16-split GEMM, 128x128 tile, BK=32, double-buffered cp.async.
// MODE 0: X @ Wqkv^T -> bf16 hi/lo q(scaled)/k/v     MODE 1: att @ Wp^T -> out
// ---------------------------------------------------------------------------
#define GBK 32
#define LDA 40
#define MAT_ELEMS (128 * LDA)
#define STAGE_ELEMS (4 * MAT_ELEMS)
#define SMEM_GEMM (2 * STAGE_ELEMS * 2)

template<int MODE>
__global__ __launch_bounds__(256) void mma_gemm_kernel(
    const float* __restrict__ bias, float* __restrict__ outp)
{
    const __nv_bfloat16* Ahi = (MODE == 0) ? g_xhi : g_ahi;
    const __nv_bfloat16* Alo = (MODE == 0) ? g_xlo : g_alo;
    const __nv_bfloat16* Bhi = (MODE == 0) ? g_wqkv_hi : g_wp_hi;
    const __nv_bfloat16* Blo = (MODE == 0) ? g_wqkv_lo : g_wp_lo;

    extern __shared__ __nv_bfloat16 sm[];
    const uint32_t sbase = smem_to_u32(sm);
    const int tid = threadIdx.x;
    const int wid = tid >> 5, lane = tid & 31;
    const int warp_m = wid & 3;
    const int warp_n = wid >> 2;
    const int m0 = blockIdx.y * 128;
    const int n0 = blockIdx.x * 128;

    float acc[2][8][4];
#pragma unroll
    for (int a = 0; a < 2; a++)
#pragma unroll
        for (int b = 0; b < 8; b++)
#pragma unroll
            for (int c = 0; c < 4; c++) acc[a][b][c] = 0.f;

    const int row = tid >> 2;
    const int un = tid & 3;

    auto load_stage = [&](int s) {
        const int buf = s & 1;
        const int k0 = s * GBK;
        const uint32_t sb = sbase + (uint32_t)buf * STAGE_ELEMS * 2;
        const __nv_bfloat16* srcs[4] = {Ahi, Alo, Bhi, Blo};
#pragma unroll
        for (int mat = 0; mat < 4; mat++) {
            const int rbase = (mat < 2) ? m0 : n0;
            const __nv_bfloat16* src = srcs[mat];
#pragma unroll
            for (int i = 0; i < 2; i++) {
                int r = row + i * 64;
                uint32_t so = sb + (uint32_t)(mat * MAT_ELEMS + r * LDA + un * 8) * 2;
                CP_ASYNC16(so, src + (size_t)(rbase + r) * C_ + k0 + un * 8);
            }
        }
        CP_COMMIT();
    };

    constexpr int NS = C_ / GBK;
    load_stage(0);

    for (int s = 0; s < NS; s++) {
        if (s + 1 < NS) { load_stage(s + 1); CP_WAIT1(); }
        else            { CP_WAIT0(); }
        __syncthreads();

        const uint32_t sb = sbase + (uint32_t)(s & 1) * STAGE_ELEMS * 2;
        const int lrow = lane & 15;
        const int lk = (lane >> 4) * 8;

#pragma unroll
        for (int kk = 0; kk < GBK; kk += 16) {
            uint32_t ah[2][4], al[2][4], bh[4][4], bl[4][4];
#pragma unroll
            for (int mt = 0; mt < 2; mt++) {
                uint32_t off = (uint32_t)((warp_m * 32 + mt * 16 + lrow) * LDA + kk + lk) * 2;
                LDSM_X4(ah[mt][0], ah[mt][1], ah[mt][2], ah[mt][3], sb + off);
                LDSM_X4(al[mt][0], al[mt][1], al[mt][2], al[mt][3],
                        sb + (uint32_t)MAT_ELEMS * 2 + off);
            }
#pragma unroll
            for (int np = 0; np < 4; np++) {
                uint32_t off = (uint32_t)((warp_n * 64 + np * 16 + lrow) * LDA + kk + lk) * 2;
                LDSM_X4(bh[np][0], bh[np][1], bh[np][2], bh[np][3],
                        sb + (uint32_t)(2 * MAT_ELEMS) * 2 + off);
                LDSM_X4(bl[np][0], bl[np][1], bl[np][2], bl[np][3],
                        sb + (uint32_t)(3 * MAT_ELEMS) * 2 + off);
            }
#pragma unroll
            for (int mt = 0; mt < 2; mt++) {
#pragma unroll
                for (int np = 0; np < 4; np++) {
#pragma unroll
                    for (int sel = 0; sel < 2; sel++) {
                        int nt = np * 2 + sel;
                        MMA16816(acc[mt][nt], ah[mt], bh[np][sel], bh[np][2 + sel]);
                        MMA16816(acc[mt][nt], ah[mt], bl[np][sel], bl[np][2 + sel]);
                        MMA16816(acc[mt][nt], al[mt], bh[np][sel], bh[np][2 + sel]);
                    }
                }
            }
        }
        __syncthreads();
    }

    // ---- epilogue ----
#pragma unroll
    for (int mt = 0; mt < 2; mt++) {
#pragma unroll
        for (int nt = 0; nt < 8; nt++) {
            int r = m0 + warp_m * 32 + mt * 16 + (lane >> 2);
            int c = n0 + warp_n * 64 + nt * 8 + (lane & 3) * 2;
            float b0 = bias[c], b1 = bias[c + 1];
            float s00 = acc[mt][nt][0] + b0, s01 = acc[mt][nt][1] + b1;
            float s10 = acc[mt][nt][2] + b0, s11 = acc[mt][nt][3] + b1;
            if (MODE == 0) {
                int bb = r >> 11, tok = r & 2047;
                int which = c >> 10, ch = c & 1023, h = ch >> 6, d0 = ch & 63;
                __nv_bfloat16* dhi = (which == 0) ? g_qhi : (which == 1) ? g_khi : g_vhi;
                __nv_bfloat16* dlo = (which == 0) ? g_qlo : (which == 1) ? g_klo : g_vlo;
                if (which == 0) { s00 *= SCALE_; s01 *= SCALE_; s10 *= SCALE_; s11 *= SCALE_; }
                size_t base = (((size_t)bb * H_ + h) * N_ + tok) * D_ + d0;
                split_store2(dhi, dlo, base, s00, s01);
                split_store2(dhi, dlo, base + 8 * D_, s10, s11);
            } else {
                *(float2*)(outp + (size_t)r * C_ + c) = make_float2(s00, s01);
                *(float2*)(outp + (size_t)(r + 8) * C_ + c) = make_float2(s10, s11);
            }
        }
    }
}

// ---------------------------------------------------------------------------
// MMA flash attention.  CTA = (b,h) x 128 queries.  8 warps x 16 rows.
// Key chunks of 64, double-buffered cp.async (Khi,Klo,Vhi,Vlo).
// 3-term bf16 split for both S=QK^T and O=PV.  Writes g_ahi/g_alo.
// ---------------------------------------------------------------------------
#define ALDK 72                            // padded row (elems)
#define AMAT (64 * ALDK)                   // 4608 elems
#define AMAT_B (AMAT * 2)                  // 9216 bytes
#define ASTAGE_B (4 * AMAT_B)              // 36864 bytes
#define SMEM_ATTN (2 * ASTAGE_B)           // 73728 bytes

__global__ __launch_bounds__(256) void attn_mma_kernel()
{
    extern __shared__ __nv_bfloat16 smx[];
    const uint32_t sb = smem_to_u32(smx);
    const int tid = threadIdx.x;
    const int wid = tid >> 5, lane = tid & 31;
    const int bh = blockIdx.x;
    const int r0t = blockIdx.y * 128;
    const size_t qoff = (size_t)bh * N_ * D_;

    // ---- stage Q tile (128x64 hi/lo) through smem, read fragments ----
#pragma unroll
    for (int i = 0; i < 4; i++) {
        int s = tid + 256 * i;             // 0..1023
        int r = s >> 3, c8 = s & 7;
        uint32_t so = (uint32_t)(r * ALDK + c8 * 8) * 2;
        *(uint4*)((char*)smx + so) =
            *(const uint4*)(g_qhi + qoff + (size_t)(r0t + r) * D_ + c8 * 8);
        *(uint4*)((char*)smx + (uint32_t)(128 * ALDK) * 2 + so) =
            *(const uint4*)(g_qlo + qoff + (size_t)(r0t + r) * D_ + c8 * 8);
    }
    __syncthreads();

    uint32_t qh[4][4], ql[4][4];
    {
        const int rb = wid * 16 + (lane & 15);
        const int cb = (lane >> 4) * 8;
#pragma unroll
        for (int kk = 0; kk < 4; kk++) {
            uint32_t addr = sb + (uint32_t)(rb * ALDK + kk * 16 + cb) * 2;
            LDSM_X4(qh[kk][0], qh[kk][1], qh[kk][2], qh[kk][3], addr);
            LDSM_X4(ql[kk][0], ql[kk][1], ql[kk][2], ql[kk][3],
                    addr + (uint32_t)(128 * ALDK) * 2);
        }
    }
    __syncthreads();

    float accO[8][4];
#pragma unroll
    for (int t = 0; t < 8; t++)
#pragma unroll
        for (int j = 0; j < 4; j++) accO[t][j] = 0.f;
    float mrow[2] = {-CUDART_INF_F, -CUDART_INF_F};
    float lrow[2] = {0.f, 0.f};

    auto load_stage = [&](int c) {
        const uint32_t base = sb + (uint32_t)(c & 1) * ASTAGE_B;
        const int k0 = c * 64;
        const __nv_bfloat16* mats[4] = {g_khi, g_klo, g_vhi, g_vlo};
#pragma unroll
        for (int i = 0; i < 8; i++) {
            int mat = i >> 1;
            int s = tid + 256 * (i & 1);   // 0..511
            int r = s >> 3, c8 = s & 7;
            uint32_t so = base + (uint32_t)mat * AMAT_B + (uint32_t)(r * ALDK + c8 * 8) * 2;
            CP_ASYNC16(so, mats[mat] + qoff + (size_t)(k0 + r) * D_ + c8 * 8);
        }
        CP_COMMIT();
    };

    load_stage(0);
    const int lr = lane & 15;
    const int lc = (lane >> 4) * 8;

    for (int c = 0; c < N_ / 64; c++) {
        if (c + 1 < N_ / 64) { load_stage(c + 1); CP_WAIT1(); }
        else                 { CP_WAIT0(); }
        __syncthreads();

        const uint32_t base = sb + (uint32_t)(c & 1) * ASTAGE_B;
        const uint32_t Kh = base, Kl = base + AMAT_B;
        const uint32_t Vh = base + 2 * AMAT_B, Vl = base + 3 * AMAT_B;

        // ---- S = Q K^T (3-term) ----
        float accS[8][4];
#pragma unroll
        for (int t = 0; t < 8; t++)
#pragma unroll
            for (int j = 0; j < 4; j++) accS[t][j] = 0.f;

#pragma unroll
        for (int kk = 0; kk < 4; kk++) {
#pragma unroll
            for (int ng = 0; ng < 4; ng++) {
                uint32_t off = (uint32_t)((ng * 16 + lr) * ALDK + kk * 16 + lc) * 2;
                uint32_t h0, h1, h2, h3, l0, l1, l2, l3;
                LDSM_X4(h0, h1, h2, h3, Kh + off);
                LDSM_X4(l0, l1, l2, l3, Kl + off);
                MMA16816(accS[2 * ng],     qh[kk], h0, h2);
                MMA16816(accS[2 * ng],     qh[kk], l0, l2);
                MMA16816(accS[2 * ng],     ql[kk], h0, h2);
                MMA16816(accS[2 * ng + 1], qh[kk], h1, h3);
                MMA16816(accS[2 * ng + 1], qh[kk], l1, l3);
                MMA16816(accS[2 * ng + 1], ql[kk], h1, h3);
            }
        }

        // ---- online softmax (q already scaled by 0.125) ----
#pragma unroll
        for (int p = 0; p < 2; p++) {
            float vm = accS[0][2 * p];
#pragma unroll
            for (int t = 0; t < 8; t++) {
                vm = fmaxf(vm, accS[t][2 * p]);
                vm = fmaxf(vm, accS[t][2 * p + 1]);
            }
            vm = fmaxf(vm, __shfl_xor_sync(0xffffffffu, vm, 1));
            vm = fmaxf(vm, __shfl_xor_sync(0xffffffffu, vm, 2));
            float mn = fmaxf(mrow[p], vm);
            float alpha = __expf(mrow[p] - mn);
            float sum = 0.f;
#pragma unroll
            for (int t = 0; t < 8; t++) {
                float e0 = __expf(accS[t][2 * p]     - mn);
                float e1 = __expf(accS[t][2 * p + 1] - mn);
                accS[t][2 * p] = e0; accS[t][2 * p + 1] = e1;
                sum += e0 + e1;
            }
            sum += __shfl_xor_sync(0xffffffffu, sum, 1);
            sum += __shfl_xor_sync(0xffffffffu, sum, 2);
            lrow[p] = lrow[p] * alpha + sum;
            mrow[p] = mn;
#pragma unroll
            for (int t = 0; t < 8; t++) {
                accO[t][2 * p]     *= alpha;
                accO[t][2 * p + 1] *= alpha;
            }
        }

        // ---- O += P V (3-term, P re-split in registers) ----
#pragma unroll
        for (int kk = 0; kk < 4; kk++) {
            uint32_t ph[4], pl[4];
            pack_split(accS[2 * kk][0],     accS[2 * kk][1],     ph[0], pl[0]);
            pack_split(accS[2 * kk][2],     accS[2 * kk][3],     ph[1], pl[1]);
            pack_split(accS[2 * kk + 1][0], accS[2 * kk + 1][1], ph[2], pl[2]);
            pack_split(accS[2 * kk + 1][2], accS[2 * kk + 1][3], ph[3], pl[3]);
#pragma unroll
            for (int dg = 0; dg < 4; dg++) {
                uint32_t off = (uint32_t)((kk * 16 + lr) * ALDK + dg * 16 + lc) * 2;
                uint32_t v0, v1, v2, v3, w0, w1, w2, w3;
                LDSM_X4_T(v0, v1, v2, v3, Vh + off);
                LDSM_X4_T(w0, w1, w2, w3, Vl + off);
                MMA16816(accO[2 * dg],     ph, v0, v1);
                MMA16816(accO[2 * dg],     pl, v0, v1);
                MMA16816(accO[2 * dg],     ph, w0, w1);
                MMA16816(accO[2 * dg + 1], ph, v2, v3);
                MMA16816(accO[2 * dg + 1], pl, v2, v3);
                MMA16816(accO[2 * dg + 1], ph, w2, w3);
            }
        }
        __syncthreads();
    }

    // ---- epilogue: normalize, split to bf16 hi/lo in [B][N][C] ----
    const int b = bh >> 4;
    const int h = bh & 15;
    const float inv0 = 1.0f / lrow[0];
    const float inv1 = 1.0f / lrow[1];
    const int row0 = r0t + wid * 16 + (lane >> 2);
#pragma unroll
    for (int t = 0; t < 8; t++) {
        int col = h * 64 + t * 8 + (lane & 3) * 2;
        split_store2(g_ahi, g_alo, ((size_t)b * N_ + row0) * C_ + col,
                     accO[t][0] * inv0, accO[t][1] * inv0);
        split_store2(g_ahi, g_alo, ((size_t)b * N_ + row0 + 8) * C_ + col,
                     accO[t][2] * inv1, accO[t][3] * inv1);
    }
}

// ---------------------------------------------------------------------------
extern "C" void kernel_launch(void* const* d_in, const int* in_sizes, int n_in,
                              void* d_out, int out_size)
{
    const float* x      = (const float*)d_in[0];
    const float* w_qkv  = (const float*)d_in[1];
    const float* b_qkv  = (const float*)d_in[2];
    const float* w_proj = (const float*)d_in[3];
    const float* b_proj = (const float*)d_in[4];
    float* out = (float*)d_out;

    cudaFuncSetAttribute(mma_gemm_kernel<0>,
                         cudaFuncAttributeMaxDynamicSharedMemorySize, SMEM_GEMM);
    cudaFuncSetAttribute(mma_gemm_kernel<1>,
                         cudaFuncAttributeMaxDynamicSharedMemorySize, SMEM_GEMM);
    cudaFuncSetAttribute(attn_mma_kernel,
                         cudaFuncAttributeMaxDynamicSharedMemorySize, SMEM_ATTN);

    // 1. Split conversions
    {
        int n4 = B_ * N_ * C_ / 4;
        split_kernel<<<(n4 + 255) / 256, 256>>>(x, n4);
        dim3 g1(3 * C_ / 32, C_ / 32);
        splitT_kernel<0><<<g1, 256>>>(w_qkv, 3 * C_);
        dim3 g2(C_ / 32, C_ / 32);
        splitT_kernel<1><<<g2, 256>>>(w_proj, C_);
    }

    // 2. QKV GEMM -> bf16 hi/lo q(scaled)/k/v
    {
        dim3 grid(3 * C_ / 128, (B_ * N_) / 128);
        mma_gemm_kernel<0><<<grid, 256, SMEM_GEMM>>>(b_qkv, nullptr);
    }

    // 3. MMA flash attention -> g_ahi/g_alo
    {
        dim3 grid(B_ * H_, N_ / 128);
        attn_mma_kernel<<<grid, 256, SMEM_ATTN>>>();
    }

    // 4. Projection GEMM -> out
    {
        dim3 grid(C_ / 128, (B_ * N_) / 128);
        mma_gemm_kernel<1><<<grid, 256, SMEM_GEMM>>>(b_proj, out);
    }
}